// round 10
// baseline (speedup 1.0000x reference)
#include <cuda_runtime.h>
#include <stdint.h>

#define D 128
#define K 16
#define TPB 128
#define WARPS 4
#define WROWS 32                // rows per warp unit; lane group p2 owns rows p2+8*rr
#define CH 16                   // columns per chunk
#define NCH 8                   // chunks per unit (D/CH)
#define ROWSTRIDE 80            // 64B data + 16B pad: conflict-free LDS.128, 16B aligned
#define STAGE_BYTES (WROWS * ROWSTRIDE)      // 2560
#define NSTAGE 3
#define WARP_STAGING (NSTAGE * STAGE_BYTES)  // 7680
#define SMEM_HDR 8448           // A (8192) + c/U + pad
#define SMEM_TOTAL (SMEM_HDR + WARPS * WARP_STAGING)  // 39168 -> 5 CTAs/SM
#define NBLK 740                // persistent: 148 SMs x 5 CTAs

// Precomputed A in (cp, k) pair-major: ull index cp*16+k holds f32x2 (A[k][2cp],A[k][2cp+1])
__device__ __align__(16) float gAp[(D / 2) * K * 2];
__device__ float gC[K];

// ---------------- helpers ----------------
__device__ __forceinline__ void ffma2(unsigned long long& c, unsigned long long a, unsigned long long b) {
    asm("fma.rn.f32x2 %0, %1, %2, %0;" : "+l"(c) : "l"(a), "l"(b));
}
__device__ __forceinline__ void unpack2(float& lo, float& hi, unsigned long long v) {
    asm("mov.b64 {%0, %1}, %2;" : "=f"(lo), "=f"(hi) : "l"(v));
}
__device__ __forceinline__ void cp_async16(uint32_t dst, const void* src, int src_bytes) {
    asm volatile("cp.async.cg.shared.global [%0], [%1], 16, %2;\n"
                 :: "r"(dst), "l"(src), "r"(src_bytes));
}
__device__ __forceinline__ void cp_commit() {
    asm volatile("cp.async.commit_group;\n" ::: "memory");
}
__device__ __forceinline__ void cp_wait2() {
    asm volatile("cp.async.wait_group 2;\n" ::: "memory");
}
__device__ __forceinline__ ulonglong2 lds128(uint32_t addr) {
    ulonglong2 q;
    asm volatile("ld.shared.v2.u64 {%0,%1}, [%2];" : "=l"(q.x), "=l"(q.y) : "r"(addr));
    return q;
}

// ---------------- merged prep (single launch) ----------------
__global__ void ntn_prep(const float* __restrict__ x2,
                         const float* __restrict__ V,
                         const float* __restrict__ W,
                         const float* __restrict__ b) {
    const int lane = threadIdx.x & 31;
    const int wid = threadIdx.x >> 5;
    const float4 x4 = ((const float4*)x2)[lane];

    if (blockIdx.x < 128) {
        const int gw = blockIdx.x * 4 + wid;        // 0..511, rows 4gw..4gw+3
        float4 w4[4];
#pragma unroll
        for (int rr = 0; rr < 4; rr++)
            w4[rr] = ((const float4*)(W + (size_t)(gw * 4 + rr) * D))[lane];
        float dots[4];
#pragma unroll
        for (int rr = 0; rr < 4; rr++)
            dots[rr] = w4[rr].x * x4.x + w4[rr].y * x4.y + w4[rr].z * x4.z + w4[rr].w * x4.w;
#pragma unroll
        for (int s = 16; s > 0; s >>= 1) {
#pragma unroll
            for (int rr = 0; rr < 4; rr++)
                dots[rr] += __shfl_xor_sync(0xffffffffu, dots[rr], s);
        }
        if (lane == 0) {
#pragma unroll
            for (int rr = 0; rr < 4; rr++) {
                const int row = gw * 4 + rr;        // = k*128 + d
                const int k = row >> 7, d = row & (D - 1);
                gAp[((d >> 1) * K + k) * 2 + (d & 1)] = V[(size_t)k * 2 * D + d] + dots[rr];
            }
        }
    } else {
#pragma unroll
        for (int kk = 0; kk < 4; kk++) {
            const int k = wid * 4 + kk;
            const float4 v4 = ((const float4*)(V + (size_t)k * 2 * D + D))[lane];
            float dot = v4.x * x4.x + v4.y * x4.y + v4.z * x4.z + v4.w * x4.w;
#pragma unroll
            for (int s = 16; s > 0; s >>= 1)
                dot += __shfl_xor_sync(0xffffffffu, dot, s);
            if (lane == 0) gC[k] = dot + b[k];
        }
    }
}

// ---------------- main: persistent, k-quarter x 4-row fragments, 3-stage per-warp pipeline ----------------
__global__ __launch_bounds__(TPB, 5)
void ntn_main(const float* __restrict__ x1,
              const float* __restrict__ U,
              float* __restrict__ out, int n, int nunits, int nw) {
    extern __shared__ __align__(16) char smem_raw[];
    unsigned long long* sA = (unsigned long long*)smem_raw;   // 1024 ull, cp-major
    float* sC = (float*)(smem_raw + 8192);
    float* sU = sC + K;

    const int tid = threadIdx.x;
    const int wid = tid >> 5;
    const int lane = tid & 31;
    const int h2 = lane & 3;         // k-quarter: owns k = h2*4 .. h2*4+3
    const int p2 = lane >> 2;        // row group: rows p2 + 8*rr, rr=0..3

    const uint32_t smem_u32 = (uint32_t)__cvta_generic_to_shared(smem_raw);
    const uint32_t sA_u32 = smem_u32;
    const uint32_t wstage_u32 = smem_u32 + SMEM_HDR + (uint32_t)wid * WARP_STAGING;
    const uint32_t xoff = (uint32_t)p2 * ROWSTRIDE;   // row rr at + rr*8*ROWSTRIDE
    const uint32_t aoff = (uint32_t)h2 * 32;          // lane's 4 k within a cp block (128B)

    // per-warp chunk issue: 32 rows x 16 cols (64B/row) -> 4 cp.async16 per lane
    auto issue = [&](int unit, int ch, int buf) {
        const uint32_t base = wstage_u32 + (uint32_t)buf * STAGE_BYTES;
        const int rowbase = unit * WROWS;
#pragma unroll
        for (int i = 0; i < 4; i++) {
            const int idx = i * 32 + lane;
            const int r = idx >> 2;          // 0..31
            const int c = idx & 3;           // float4 within 64B row-chunk
            const int grow = rowbase + r;
            const int ok = (grow < n);
            const float* src = x1 + (size_t)(ok ? grow : 0) * D + ch * CH + c * 4;
            cp_async16(base + (uint32_t)(r * ROWSTRIDE + c * 16), src, ok ? 16 : 0);
        }
    };

    const int gw0 = blockIdx.x * WARPS + wid;

    // prologue: chunks 0,1 of first unit in flight before header load
    if (gw0 < nunits) { issue(gw0, 0, 0); cp_commit(); issue(gw0, 1, 1); cp_commit(); }
    else { cp_commit(); cp_commit(); }

    // header: A, c, U (single block barrier in whole kernel)
    {
        const unsigned long long* gAu = (const unsigned long long*)gAp;
#pragma unroll
        for (int i = 0; i < 8; i++) sA[tid + i * TPB] = gAu[tid + i * TPB];
        if (tid < K) { sC[tid] = gC[tid]; sU[tid] = U[tid]; }
    }
    __syncthreads();

    int buf = 0;   // buffer of the chunk being consumed
    for (int u = gw0; u < nunits; u += nw) {
        unsigned long long acc[4][4];    // [row rr][k j]; k = h2*4 + j
#pragma unroll
        for (int rr = 0; rr < 4; rr++)
#pragma unroll
            for (int j = 0; j < 4; j++) acc[rr][j] = 0ull;

#pragma unroll 1
        for (int ch = 0; ch < NCH; ch++) {
            // issue chunk ch+2 of the stream (wraps into next unit)
            {
                int c2 = ch + 2, u2 = u;
                if (c2 >= NCH) { c2 -= NCH; u2 += nw; }
                int b2 = buf + 2; if (b2 >= NSTAGE) b2 -= NSTAGE;
                if (u2 < nunits) issue(u2, c2, b2);
            }
            cp_commit();
            cp_wait2();                 // <=2 pending => chunk ch landed
            __syncwarp();

            const uint32_t wb = wstage_u32 + (uint32_t)buf * STAGE_BYTES + xoff;
            const uint32_t ab = sA_u32 + (uint32_t)(ch * 8) * 128 + aoff;
#pragma unroll
            for (int q = 0; q < 4; q++) {          // 16B quads of the 64B chunk-row
                ulonglong2 xq[4];
#pragma unroll
                for (int rr = 0; rr < 4; rr++)
                    xq[rr] = lds128(wb + (uint32_t)(rr * 8 * ROWSTRIDE + q * 16));
#pragma unroll
                for (int e = 0; e < 2; e++) {      // col-pair within quad
                    const uint32_t acp = ab + (uint32_t)(q * 2 + e) * 128;
                    const ulonglong2 a01 = lds128(acp);        // k = h2*4, h2*4+1
                    const ulonglong2 a23 = lds128(acp + 16);   // k = h2*4+2, h2*4+3
#pragma unroll
                    for (int rr = 0; rr < 4; rr++) {
                        const unsigned long long xv = e ? xq[rr].y : xq[rr].x;
                        ffma2(acc[rr][0], xv, a01.x);
                        ffma2(acc[rr][1], xv, a01.y);
                        ffma2(acc[rr][2], xv, a23.x);
                        ffma2(acc[rr][3], xv, a23.y);
                    }
                }
            }
            __syncwarp();      // WAR: all lanes done with buf before it is re-issued
            if (++buf == NSTAGE) buf = 0;
        }

        // epilogue: per-row partial over lane's 4 k, reduce across the 4-lane k-group
#pragma unroll
        for (int rr = 0; rr < 4; rr++) {
            float part = 0.f;
#pragma unroll
            for (int j = 0; j < 4; j++) {
                float lo, hi;
                unpack2(lo, hi, acc[rr][j]);
                const int k = h2 * 4 + j;
                const float s = lo + hi + sC[k];
                part = fmaf(fmaxf(s, 0.f), sU[k], part);
            }
            part += __shfl_xor_sync(0xffffffffu, part, 1);
            part += __shfl_xor_sync(0xffffffffu, part, 2);
            const int row = u * WROWS + rr * 8 + p2;
            if (h2 == 0 && row < n) out[row] = part;
        }
    }
    asm volatile("cp.async.wait_all;\n" ::: "memory");
}

// ---------------- launch ----------------
extern "C" void kernel_launch(void* const* d_in, const int* in_sizes, int n_in,
                              void* d_out, int out_size) {
    const float* x1 = nullptr; const float* x2 = nullptr; const float* V = nullptr;
    const float* W = nullptr;  const float* b = nullptr;  const float* U = nullptr;
    int n16 = 0;
    for (int i = 0; i < n_in; i++) {
        const int s = in_sizes[i];
        const float* p = (const float*)d_in[i];
        if (s == 128) x2 = p;
        else if (s == 4096) V = p;
        else if (s == 262144) W = p;
        else if (s == 16) { if (n16++ == 0) b = p; else U = p; }
        else x1 = p;
    }
    int n = 0;
    for (int i = 0; i < n_in; i++) if ((const float*)d_in[i] == x1) n = in_sizes[i] / D;

    float* out = (float*)d_out;

    ntn_prep<<<129, TPB>>>(x2, V, W, b);

    const int nunits = (n + WROWS - 1) / WROWS;
    int blocks = (nunits + WARPS - 1) / WARPS;
    if (blocks > NBLK) blocks = NBLK;
    const int nw = blocks * WARPS;
    cudaFuncSetAttribute(ntn_main, cudaFuncAttributeMaxDynamicSharedMemorySize, SMEM_TOTAL);
    ntn_main<<<blocks, TPB, SMEM_TOTAL>>>(x1, U, out, n, nunits, nw);
}